// round 14
// baseline (speedup 1.0000x reference)
#include <cuda_runtime.h>
#include <cuda_bf16.h>
#include <cstdint>
#include <cstddef>

// ============================================================================
// Problem constants
// ============================================================================
#define D_DIM   2048
#define M_TOTAL 16384

// GEMM tiling (CHAMPION config: persistent, BK64, 4-stage, occ3, hybrid 2xdp4a)
#define BM 128
#define BN 64
#define BK 64
#define NK (D_DIM / BK)          // 32 k-tiles
#define N_MP (M_TOTAL / BM)      // 128 m-panels
#define N_NP (D_DIM / BN)        // 32 n-panels
#define NTILES (N_MP * N_NP)     // 4096
#define STAGES 4
#define ROW_PITCH 80             // 64B row + 16B pad -> conflict-free LDS/LDSM
#define A_STG (BM * ROW_PITCH)   // 10240 B
#define B_STG (BN * ROW_PITCH)   // 5120 B
#define STG_BYTES (A_STG + B_STG)
#define SB_OFF A_STG
#define AEFF_OFF (STAGES * STG_BYTES)        // 61440
#define SMEM_NEED_G (AEFF_OFF + BN * 4 + 16) // 61712 B

// Hybrid split: warps 0..1 dp4a on rows [0,32); warps 2..7 IMMA on rows [32,128)
#define N_DP4A_WARPS 2
#define DP_ROWS      32
#define IMMA_ROW0    DP_ROWS

// ============================================================================
// Scratch (device globals; allocation is forbidden)
// ============================================================================
__device__ int8_t g_eq[(size_t)M_TOTAL * D_DIM];   // 32 MB int8 codes of e
__device__ int8_t g_wq[(size_t)D_DIM * D_DIM];     // 4 MB ternary codes of W
__device__ float  g_crow[M_TOTAL];                 // per-row absmax/127
__device__ float  g_partial[D_DIM];                // |W| partial sums
__device__ float  g_wmean;                         // clip(mean|W|, eps)
__device__ int    g_ticket;                        // dynamic tile ticket

// ============================================================================
// PTX helpers (sm_80-era, valid at compute_103)
// ============================================================================
__device__ __forceinline__ uint32_t smem_u32(const void* p) {
    uint32_t a;
    asm("{ .reg .u64 t; cvta.to.shared.u64 t, %1; cvt.u32.u64 %0, t; }"
        : "=r"(a) : "l"(p));
    return a;
}

__device__ __forceinline__ void cp_async16(uint32_t saddr, const void* gaddr) {
    asm volatile("cp.async.cg.shared.global [%0], [%1], 16;"
                 :: "r"(saddr), "l"(gaddr) : "memory");
}
__device__ __forceinline__ void cp_commit() {
    asm volatile("cp.async.commit_group;" ::: "memory");
}
template <int N>
__device__ __forceinline__ void cp_wait() {
    asm volatile("cp.async.wait_group %0;" :: "n"(N) : "memory");
}

__device__ __forceinline__ void ldsm_x4(uint32_t* r, uint32_t addr) {
    asm volatile("ldmatrix.sync.aligned.m8n8.x4.shared.b16 {%0,%1,%2,%3}, [%4];"
                 : "=r"(r[0]), "=r"(r[1]), "=r"(r[2]), "=r"(r[3]) : "r"(addr));
}

__device__ __forceinline__ void mma_s8(int* c, const uint32_t* a, const uint32_t* b) {
    asm volatile(
        "mma.sync.aligned.m16n8k32.row.col.s32.s8.s8.s32 "
        "{%0,%1,%2,%3}, {%4,%5,%6,%7}, {%8,%9}, {%0,%1,%2,%3};"
        : "+r"(c[0]), "+r"(c[1]), "+r"(c[2]), "+r"(c[3])
        : "r"(a[0]), "r"(a[1]), "r"(a[2]), "r"(a[3]), "r"(b[0]), "r"(b[1]));
}

// ============================================================================
// Kernel 1 (fused): blocks [0, M_TOTAL)        -> per-row int8 quant of e
//                   blocks [M_TOTAL, +D_DIM)   -> per-row sum|W| partials
// Block 0 also resets the GEMM ticket.
// ============================================================================
__global__ void __launch_bounds__(256) preproc_kernel(const float* __restrict__ e,
                                                      const float* __restrict__ W) {
    __shared__ float red[256];
    const int tid = threadIdx.x;
    if (blockIdx.x == 0 && tid == 0) g_ticket = 0;

    if (blockIdx.x < M_TOTAL) {
        const int row = blockIdx.x;
        const float4* ep = (const float4*)(e + (size_t)row * D_DIM);

        float4 v0 = ep[tid];
        float4 v1 = ep[tid + 256];
        float am = fmaxf(fmaxf(fabsf(v0.x), fabsf(v0.y)), fmaxf(fabsf(v0.z), fabsf(v0.w)));
        am = fmaxf(am, fmaxf(fmaxf(fabsf(v1.x), fabsf(v1.y)), fmaxf(fabsf(v1.z), fabsf(v1.w))));
        #pragma unroll
        for (int o = 16; o > 0; o >>= 1)
            am = fmaxf(am, __shfl_xor_sync(0xFFFFFFFFu, am, o));
        if ((tid & 31) == 0) red[tid >> 5] = am;
        __syncthreads();
        if (tid == 0) {
            float a = red[0];
            #pragma unroll
            for (int i = 1; i < 8; i++) a = fmaxf(a, red[i]);
            red[0] = fmaxf(a, 1e-5f);
        }
        __syncthreads();
        const float amax = red[0];
        const float scale = 127.0f / amax;

        char4* eqp = ((char4*)g_eq) + (size_t)row * (D_DIM / 4);
        {
            char4 q;
            q.x = (char)(int)fminf(fmaxf(rintf(v0.x * scale), -128.f), 127.f);
            q.y = (char)(int)fminf(fmaxf(rintf(v0.y * scale), -128.f), 127.f);
            q.z = (char)(int)fminf(fmaxf(rintf(v0.z * scale), -128.f), 127.f);
            q.w = (char)(int)fminf(fmaxf(rintf(v0.w * scale), -128.f), 127.f);
            eqp[tid] = q;
        }
        {
            char4 q;
            q.x = (char)(int)fminf(fmaxf(rintf(v1.x * scale), -128.f), 127.f);
            q.y = (char)(int)fminf(fmaxf(rintf(v1.y * scale), -128.f), 127.f);
            q.z = (char)(int)fminf(fmaxf(rintf(v1.z * scale), -128.f), 127.f);
            q.w = (char)(int)fminf(fmaxf(rintf(v1.w * scale), -128.f), 127.f);
            eqp[tid + 256] = q;
        }
        if (tid == 0) g_crow[row] = amax / 127.0f;
    } else {
        const int wrow = blockIdx.x - M_TOTAL;
        const float4* p = (const float4*)(W + (size_t)wrow * D_DIM);
        float acc = 0.f;
        #pragma unroll
        for (int k = 0; k < 2; k++) {
            float4 v = p[tid + k * 256];
            acc += fabsf(v.x) + fabsf(v.y) + fabsf(v.z) + fabsf(v.w);
        }
        red[tid] = acc;
        __syncthreads();
        for (int st = 128; st > 0; st >>= 1) {
            if (tid < st) red[tid] += red[tid + st];
            __syncthreads();
        }
        if (tid == 0) g_partial[wrow] = red[0];
    }
}

// ============================================================================
// Kernel 2: fused mean(|W|) (redundant per CTA, deterministic) + ternary quant
// W load hoisted ABOVE the reduction so its latency overlaps the smem work.
// ============================================================================
__global__ void __launch_bounds__(256) quant_w_kernel(const float* __restrict__ W) {
    __shared__ float s[256];
    const int tid = threadIdx.x;

    // hoisted independent global load (latency overlaps the reduction below)
    const size_t idx = (size_t)blockIdx.x * 256 + tid;
    float4 v = ((const float4*)W)[idx];

    float acc = 0.f;
    #pragma unroll
    for (int k = 0; k < 8; k++) acc += g_partial[tid + k * 256];
    s[tid] = acc;
    __syncthreads();
    for (int st = 128; st > 0; st >>= 1) {
        if (tid < st) s[tid] += s[tid + st];
        __syncthreads();
    }
    const float wmean = fmaxf(s[0] / 4194304.0f, 1e-5f);
    if (blockIdx.x == 0 && tid == 0) g_wmean = wmean;

    const float inv = 1.0f / wmean;
    char4 q;
    q.x = (char)(int)fminf(fmaxf(rintf(v.x * inv), -1.f), 1.f);
    q.y = (char)(int)fminf(fmaxf(rintf(v.y * inv), -1.f), 1.f);
    q.z = (char)(int)fminf(fmaxf(rintf(v.z * inv), -1.f), 1.f);
    q.w = (char)(int)fminf(fmaxf(rintf(v.w * inv), -1.f), 1.f);
    ((char4*)g_wq)[idx] = q;
}

// ============================================================================
// Kernel 3 (CHAMPION + int2 dp4a loads): persistent hybrid IMMA + dp4a GEMM
//   warps 2..7: tensor path, rows [32,128) of the tile (warp tile 16x64)
//   warps 0..1: dp4a path on fma/alu pipes, rows [0,32)
//   out[m][n] = crow[m]*wmean*acc + 0.99*tanh(A_raw[n])*h + block_out
// ============================================================================
__global__ void __launch_bounds__(256, 3) gemm_bitlinear_kernel(
    const float* __restrict__ hh,
    const float* __restrict__ bo,
    const float* __restrict__ a_raw,
    float* __restrict__ outp)
{
    extern __shared__ char smem[];
    const uint32_t sbase = smem_u32(smem);
    float* sAeff = (float*)(smem + AEFF_OFF);
    int* sTicket = (int*)(smem + AEFF_OFF + BN * 4);

    const int tid = threadIdx.x;
    const int wid = tid >> 5;
    const int lane = tid & 31;
    const float wmean = g_wmean;

    // prefetch thread coords (all threads)
    const int a0row = tid >> 2, a0col = (tid & 3) * 16;
    const int a1row = (tid + 256) >> 2;
    const int brow  = tid >> 2;

    // IMMA-path constants (warps 2..7)
    const int lq = lane >> 2;
    const int lr = lane & 3;
    const uint32_t lm_row  = (uint32_t)(lane & 15);
    const uint32_t lm_half = (uint32_t)((lane >> 4) * 16);
    const int iw = wid - N_DP4A_WARPS;            // 0..5 for imma warps
    const uint32_t aOffW = (uint32_t)((IMMA_ROW0 + iw * 16) + (int)lm_row) * ROW_PITCH + lm_half;
    const uint32_t bOffW = lm_row * ROW_PITCH + lm_half;

    // dp4a-path constants (warps 0..1): thread grid 4(ty) x 16(tx)
    const int ty = (wid << 1) | (lane >> 4);      // 0..3
    const int tx = lane & 15;

    for (;;) {
        if (tid == 0) *sTicket = atomicAdd(&g_ticket, 1);
        __syncthreads();
        const int t = *sTicket;
        if (t >= NTILES) break;
        const int m_base = (t >> 5) * BM;
        const int n_base = (t & 31) * BN;

        if (tid < BN) sAeff[tid] = 0.99f * tanhf(a_raw[n_base + tid]);

        const int8_t* Ag = g_eq + (size_t)m_base * D_DIM;
        const int8_t* Bg = g_wq + (size_t)n_base * D_DIM;

        auto prefetch = [&](int kt) {
            const int s = kt % STAGES;
            const int k0 = kt * BK;
            const uint32_t sA = sbase + s * STG_BYTES;
            const uint32_t sB = sA + SB_OFF;
            cp_async16(sA + a0row * ROW_PITCH + a0col, Ag + (size_t)a0row * D_DIM + k0 + a0col);
            cp_async16(sA + a1row * ROW_PITCH + a0col, Ag + (size_t)a1row * D_DIM + k0 + a0col);
            cp_async16(sB + brow * ROW_PITCH + a0col,  Bg + (size_t)brow * D_DIM + k0 + a0col);
        };

        prefetch(0); cp_commit();
        prefetch(1); cp_commit();
        prefetch(2); cp_commit();

        if (wid >= N_DP4A_WARPS) {
            // ================= tensor path: 96 rows, warp tile 16x64 =========
            int acc[8][4];
            #pragma unroll
            for (int j = 0; j < 8; j++)
                #pragma unroll
                for (int r = 0; r < 4; r++) acc[j][r] = 0;

            for (int kt = 0; kt < NK; ++kt) {
                cp_wait<2>();
                __syncthreads();
                if (kt + 3 < NK) prefetch(kt + 3);
                cp_commit();

                const int s = kt % STAGES;
                const uint32_t aBase = sbase + s * STG_BYTES + aOffW;
                const uint32_t bBase = sbase + s * STG_BYTES + SB_OFF + bOffW;

                #pragma unroll
                for (int ks = 0; ks < 2; ks++) {
                    const int ko = ks * 32;
                    uint32_t a[4], b[8][2];
                    ldsm_x4(a, aBase + ko);
                    #pragma unroll
                    for (int jj = 0; jj < 4; jj++) {
                        uint32_t r[4];
                        ldsm_x4(r, bBase + jj * 16 * ROW_PITCH + ko);
                        b[2 * jj][0]     = r[0];
                        b[2 * jj + 1][0] = r[1];
                        b[2 * jj][1]     = r[2];
                        b[2 * jj + 1][1] = r[3];
                    }
                    #pragma unroll
                    for (int j = 0; j < 8; j++)
                        mma_s8(acc[j], a, b[j]);
                }
            }

            // epilogue (tensor rows)
            const int m0 = m_base + IMMA_ROW0 + iw * 16 + lq;
            const int m1 = m0 + 8;
            const float cs0 = g_crow[m0] * wmean;
            const float cs1 = g_crow[m1] * wmean;
            const float* h0 = hh + (size_t)m0 * D_DIM;
            const float* h1 = hh + (size_t)m1 * D_DIM;
            const float* b0 = bo + (size_t)m0 * D_DIM;
            const float* b1 = bo + (size_t)m1 * D_DIM;
            float* o0 = outp + (size_t)m0 * D_DIM;
            float* o1 = outp + (size_t)m1 * D_DIM;
            #pragma unroll
            for (int j = 0; j < 8; j++) {
                const int nl = j * 8 + lr * 2;
                const int n = n_base + nl;
                const float ax = sAeff[nl], ay = sAeff[nl + 1];
                {
                    float2 hv = *(const float2*)(h0 + n);
                    float2 bv = *(const float2*)(b0 + n);
                    float2 o;
                    o.x = cs0 * (float)acc[j][0] + ax * hv.x + bv.x;
                    o.y = cs0 * (float)acc[j][1] + ay * hv.y + bv.y;
                    *(float2*)(o0 + n) = o;
                }
                {
                    float2 hv = *(const float2*)(h1 + n);
                    float2 bv = *(const float2*)(b1 + n);
                    float2 o;
                    o.x = cs1 * (float)acc[j][2] + ax * hv.x + bv.x;
                    o.y = cs1 * (float)acc[j][3] + ay * hv.y + bv.y;
                    *(float2*)(o1 + n) = o;
                }
            }
        } else {
            // ================= dp4a path: rows [0,32), 8m x 4n per thread ====
            // int2 operand loads: halves LDS issue count vs scalar int.
            int acc[8][4];
            #pragma unroll
            for (int i = 0; i < 8; i++)
                #pragma unroll
                for (int j = 0; j < 4; j++) acc[i][j] = 0;

            for (int kt = 0; kt < NK; ++kt) {
                cp_wait<2>();
                __syncthreads();
                if (kt + 3 < NK) prefetch(kt + 3);
                cp_commit();

                const int s = kt % STAGES;
                const char* tA = smem + s * STG_BYTES;
                const char* tB = tA + SB_OFF;

                #pragma unroll 2
                for (int kk = 0; kk < 16; kk += 2) {
                    int2 Bw[4], Aw[8];
                    #pragma unroll
                    for (int j = 0; j < 4; j++)
                        Bw[j] = *(const int2*)(tB + (tx + 16 * j) * ROW_PITCH + kk * 4);
                    #pragma unroll
                    for (int i = 0; i < 8; i++)
                        Aw[i] = *(const int2*)(tA + (ty + 4 * i) * ROW_PITCH + kk * 4);
                    #pragma unroll
                    for (int i = 0; i < 8; i++)
                        #pragma unroll
                        for (int j = 0; j < 4; j++) {
                            acc[i][j] = __dp4a(Aw[i].x, Bw[j].x, acc[i][j]);
                            acc[i][j] = __dp4a(Aw[i].y, Bw[j].y, acc[i][j]);
                        }
                }
            }

            // epilogue (dp4a rows)
            #pragma unroll
            for (int i = 0; i < 8; i++) {
                const int m = m_base + ty + 4 * i;
                const float cs = g_crow[m] * wmean;
                const float* hr = hh + (size_t)m * D_DIM + n_base;
                const float* br = bo + (size_t)m * D_DIM + n_base;
                float* orow = outp + (size_t)m * D_DIM + n_base;
                #pragma unroll
                for (int j = 0; j < 4; j++) {
                    const int nl = tx + 16 * j;
                    orow[nl] = cs * (float)acc[i][j] + sAeff[nl] * hr[nl] + br[nl];
                }
            }
        }
        __syncthreads();   // smem reuse safety across tiles
    }
}

// ============================================================================
// Host launcher — 3 launches
// ============================================================================
extern "C" void kernel_launch(void* const* d_in, const int* in_sizes, int n_in,
                              void* d_out, int out_size) {
    const float* hh   = (const float*)d_in[0];
    const float* e    = (const float*)d_in[1];
    const float* bo   = (const float*)d_in[2];
    const float* araw = (const float*)d_in[3];
    const float* W    = (const float*)d_in[4];
    float* outp = (float*)d_out;

    static int sms = 148;
    static bool init_done = false;
    if (!init_done) {
        cudaDeviceGetAttribute(&sms, cudaDevAttrMultiProcessorCount, 0);
        cudaFuncSetAttribute(gemm_bitlinear_kernel,
                             cudaFuncAttributeMaxDynamicSharedMemorySize, SMEM_NEED_G);
        init_done = true;
    }

    preproc_kernel<<<M_TOTAL + D_DIM, 256>>>(e, W);
    quant_w_kernel<<<(D_DIM * (size_t)D_DIM) / 1024, 256>>>(W);
    gemm_bitlinear_kernel<<<3 * sms, 256, SMEM_NEED_G>>>(hh, bo, araw, outp);
}

// round 15
// speedup vs baseline: 1.0380x; 1.0380x over previous
#include <cuda_runtime.h>
#include <cuda_bf16.h>
#include <cstdint>
#include <cstddef>

// ============================================================================
// Problem constants
// ============================================================================
#define D_DIM   2048
#define M_TOTAL 16384

// GEMM tiling (CHAMPION config: persistent, BK64, 4-stage, occ3, hybrid 2xdp4a)
#define BM 128
#define BN 64
#define BK 64
#define NK (D_DIM / BK)          // 32 k-tiles
#define N_MP (M_TOTAL / BM)      // 128 m-panels
#define N_NP (D_DIM / BN)        // 32 n-panels
#define NTILES (N_MP * N_NP)     // 4096
#define STAGES 4
#define ROW_PITCH 80             // 64B row + 16B pad -> conflict-free LDS/LDSM
#define A_STG (BM * ROW_PITCH)   // 10240 B
#define B_STG (BN * ROW_PITCH)   // 5120 B
#define STG_BYTES (A_STG + B_STG)
#define SB_OFF A_STG
#define AEFF_OFF (STAGES * STG_BYTES)        // 61440
#define SMEM_NEED_G (AEFF_OFF + BN * 4 + 16) // 61712 B

// Hybrid split: warps 0..1 dp4a on rows [0,32); warps 2..7 IMMA on rows [32,128)
#define N_DP4A_WARPS 2
#define DP_ROWS      32
#define IMMA_ROW0    DP_ROWS

// ============================================================================
// Scratch (device globals; allocation is forbidden)
// ============================================================================
__device__ int8_t g_eq[(size_t)M_TOTAL * D_DIM];   // 32 MB int8 codes of e
__device__ int8_t g_wq[(size_t)D_DIM * D_DIM];     // 4 MB ternary codes of W
__device__ float  g_crow[M_TOTAL];                 // per-row absmax/127
__device__ float  g_partial[D_DIM];                // |W| partial sums
__device__ float  g_wmean;                         // clip(mean|W|, eps)
__device__ int    g_ticket;                        // dynamic tile ticket

// ============================================================================
// PTX helpers (sm_80-era, valid at compute_103)
// ============================================================================
__device__ __forceinline__ uint32_t smem_u32(const void* p) {
    uint32_t a;
    asm("{ .reg .u64 t; cvta.to.shared.u64 t, %1; cvt.u32.u64 %0, t; }"
        : "=r"(a) : "l"(p));
    return a;
}

__device__ __forceinline__ void cp_async16(uint32_t saddr, const void* gaddr) {
    asm volatile("cp.async.cg.shared.global [%0], [%1], 16;"
                 :: "r"(saddr), "l"(gaddr) : "memory");
}
__device__ __forceinline__ void cp_commit() {
    asm volatile("cp.async.commit_group;" ::: "memory");
}
template <int N>
__device__ __forceinline__ void cp_wait() {
    asm volatile("cp.async.wait_group %0;" :: "n"(N) : "memory");
}

__device__ __forceinline__ void ldsm_x4(uint32_t* r, uint32_t addr) {
    asm volatile("ldmatrix.sync.aligned.m8n8.x4.shared.b16 {%0,%1,%2,%3}, [%4];"
                 : "=r"(r[0]), "=r"(r[1]), "=r"(r[2]), "=r"(r[3]) : "r"(addr));
}

__device__ __forceinline__ void mma_s8(int* c, const uint32_t* a, const uint32_t* b) {
    asm volatile(
        "mma.sync.aligned.m16n8k32.row.col.s32.s8.s8.s32 "
        "{%0,%1,%2,%3}, {%4,%5,%6,%7}, {%8,%9}, {%0,%1,%2,%3};"
        : "+r"(c[0]), "+r"(c[1]), "+r"(c[2]), "+r"(c[3])
        : "r"(a[0]), "r"(a[1]), "r"(a[2]), "r"(a[3]), "r"(b[0]), "r"(b[1]));
}

// ============================================================================
// Kernel 1 (fused): blocks [0, M_TOTAL)        -> per-row int8 quant of e
//                   blocks [M_TOTAL, +D_DIM)   -> per-row sum|W| partials
// Block 0 also resets the GEMM ticket.
// ============================================================================
__global__ void __launch_bounds__(256) preproc_kernel(const float* __restrict__ e,
                                                      const float* __restrict__ W) {
    __shared__ float red[256];
    const int tid = threadIdx.x;
    if (blockIdx.x == 0 && tid == 0) g_ticket = 0;

    if (blockIdx.x < M_TOTAL) {
        const int row = blockIdx.x;
        const float4* ep = (const float4*)(e + (size_t)row * D_DIM);

        float4 v0 = ep[tid];
        float4 v1 = ep[tid + 256];
        float am = fmaxf(fmaxf(fabsf(v0.x), fabsf(v0.y)), fmaxf(fabsf(v0.z), fabsf(v0.w)));
        am = fmaxf(am, fmaxf(fmaxf(fabsf(v1.x), fabsf(v1.y)), fmaxf(fabsf(v1.z), fabsf(v1.w))));
        #pragma unroll
        for (int o = 16; o > 0; o >>= 1)
            am = fmaxf(am, __shfl_xor_sync(0xFFFFFFFFu, am, o));
        if ((tid & 31) == 0) red[tid >> 5] = am;
        __syncthreads();
        if (tid == 0) {
            float a = red[0];
            #pragma unroll
            for (int i = 1; i < 8; i++) a = fmaxf(a, red[i]);
            red[0] = fmaxf(a, 1e-5f);
        }
        __syncthreads();
        const float amax = red[0];
        const float scale = 127.0f / amax;

        char4* eqp = ((char4*)g_eq) + (size_t)row * (D_DIM / 4);
        {
            char4 q;
            q.x = (char)(int)fminf(fmaxf(rintf(v0.x * scale), -128.f), 127.f);
            q.y = (char)(int)fminf(fmaxf(rintf(v0.y * scale), -128.f), 127.f);
            q.z = (char)(int)fminf(fmaxf(rintf(v0.z * scale), -128.f), 127.f);
            q.w = (char)(int)fminf(fmaxf(rintf(v0.w * scale), -128.f), 127.f);
            eqp[tid] = q;
        }
        {
            char4 q;
            q.x = (char)(int)fminf(fmaxf(rintf(v1.x * scale), -128.f), 127.f);
            q.y = (char)(int)fminf(fmaxf(rintf(v1.y * scale), -128.f), 127.f);
            q.z = (char)(int)fminf(fmaxf(rintf(v1.z * scale), -128.f), 127.f);
            q.w = (char)(int)fminf(fmaxf(rintf(v1.w * scale), -128.f), 127.f);
            eqp[tid + 256] = q;
        }
        if (tid == 0) g_crow[row] = amax / 127.0f;
    } else {
        const int wrow = blockIdx.x - M_TOTAL;
        const float4* p = (const float4*)(W + (size_t)wrow * D_DIM);
        float acc = 0.f;
        #pragma unroll
        for (int k = 0; k < 2; k++) {
            float4 v = p[tid + k * 256];
            acc += fabsf(v.x) + fabsf(v.y) + fabsf(v.z) + fabsf(v.w);
        }
        red[tid] = acc;
        __syncthreads();
        for (int st = 128; st > 0; st >>= 1) {
            if (tid < st) red[tid] += red[tid + st];
            __syncthreads();
        }
        if (tid == 0) g_partial[wrow] = red[0];
    }
}

// ============================================================================
// Kernel 2: fused mean(|W|) (redundant per CTA, deterministic) + ternary quant
// ============================================================================
__global__ void __launch_bounds__(256) quant_w_kernel(const float* __restrict__ W) {
    __shared__ float s[256];
    const int tid = threadIdx.x;
    float acc = 0.f;
    #pragma unroll
    for (int k = 0; k < 8; k++) acc += g_partial[tid + k * 256];
    s[tid] = acc;
    __syncthreads();
    for (int st = 128; st > 0; st >>= 1) {
        if (tid < st) s[tid] += s[tid + st];
        __syncthreads();
    }
    const float wmean = fmaxf(s[0] / 4194304.0f, 1e-5f);
    if (blockIdx.x == 0 && tid == 0) g_wmean = wmean;

    const float inv = 1.0f / wmean;
    const size_t idx = (size_t)blockIdx.x * 256 + tid;
    float4 v = ((const float4*)W)[idx];
    char4 q;
    q.x = (char)(int)fminf(fmaxf(rintf(v.x * inv), -1.f), 1.f);
    q.y = (char)(int)fminf(fmaxf(rintf(v.y * inv), -1.f), 1.f);
    q.z = (char)(int)fminf(fmaxf(rintf(v.z * inv), -1.f), 1.f);
    q.w = (char)(int)fminf(fmaxf(rintf(v.w * inv), -1.f), 1.f);
    ((char4*)g_wq)[idx] = q;
}

// ============================================================================
// Kernel 3 (CHAMPION): persistent hybrid IMMA + dp4a GEMM + fused epilogue
//   warps 2..7: tensor path, rows [32,128) of the tile (warp tile 16x64)
//   warps 0..1: dp4a path on fma/alu pipes, rows [0,32) — scalar LDS.32 loads
//   out[m][n] = crow[m]*wmean*acc + 0.99*tanh(A_raw[n])*h + block_out
// ============================================================================
__global__ void __launch_bounds__(256, 3) gemm_bitlinear_kernel(
    const float* __restrict__ hh,
    const float* __restrict__ bo,
    const float* __restrict__ a_raw,
    float* __restrict__ outp)
{
    extern __shared__ char smem[];
    const uint32_t sbase = smem_u32(smem);
    float* sAeff = (float*)(smem + AEFF_OFF);
    int* sTicket = (int*)(smem + AEFF_OFF + BN * 4);

    const int tid = threadIdx.x;
    const int wid = tid >> 5;
    const int lane = tid & 31;
    const float wmean = g_wmean;

    // prefetch thread coords (all threads)
    const int a0row = tid >> 2, a0col = (tid & 3) * 16;
    const int a1row = (tid + 256) >> 2;
    const int brow  = tid >> 2;

    // IMMA-path constants (warps 2..7)
    const int lq = lane >> 2;
    const int lr = lane & 3;
    const uint32_t lm_row  = (uint32_t)(lane & 15);
    const uint32_t lm_half = (uint32_t)((lane >> 4) * 16);
    const int iw = wid - N_DP4A_WARPS;            // 0..5 for imma warps
    const uint32_t aOffW = (uint32_t)((IMMA_ROW0 + iw * 16) + (int)lm_row) * ROW_PITCH + lm_half;
    const uint32_t bOffW = lm_row * ROW_PITCH + lm_half;

    // dp4a-path constants (warps 0..1): thread grid 4(ty) x 16(tx)
    const int ty = (wid << 1) | (lane >> 4);      // 0..3
    const int tx = lane & 15;

    for (;;) {
        if (tid == 0) *sTicket = atomicAdd(&g_ticket, 1);
        __syncthreads();
        const int t = *sTicket;
        if (t >= NTILES) break;
        const int m_base = (t >> 5) * BM;
        const int n_base = (t & 31) * BN;

        if (tid < BN) sAeff[tid] = 0.99f * tanhf(a_raw[n_base + tid]);

        const int8_t* Ag = g_eq + (size_t)m_base * D_DIM;
        const int8_t* Bg = g_wq + (size_t)n_base * D_DIM;

        auto prefetch = [&](int kt) {
            const int s = kt % STAGES;
            const int k0 = kt * BK;
            const uint32_t sA = sbase + s * STG_BYTES;
            const uint32_t sB = sA + SB_OFF;
            cp_async16(sA + a0row * ROW_PITCH + a0col, Ag + (size_t)a0row * D_DIM + k0 + a0col);
            cp_async16(sA + a1row * ROW_PITCH + a0col, Ag + (size_t)a1row * D_DIM + k0 + a0col);
            cp_async16(sB + brow * ROW_PITCH + a0col,  Bg + (size_t)brow * D_DIM + k0 + a0col);
        };

        prefetch(0); cp_commit();
        prefetch(1); cp_commit();
        prefetch(2); cp_commit();

        if (wid >= N_DP4A_WARPS) {
            // ================= tensor path: 96 rows, warp tile 16x64 =========
            int acc[8][4];
            #pragma unroll
            for (int j = 0; j < 8; j++)
                #pragma unroll
                for (int r = 0; r < 4; r++) acc[j][r] = 0;

            for (int kt = 0; kt < NK; ++kt) {
                cp_wait<2>();
                __syncthreads();
                if (kt + 3 < NK) prefetch(kt + 3);
                cp_commit();

                const int s = kt % STAGES;
                const uint32_t aBase = sbase + s * STG_BYTES + aOffW;
                const uint32_t bBase = sbase + s * STG_BYTES + SB_OFF + bOffW;

                #pragma unroll
                for (int ks = 0; ks < 2; ks++) {
                    const int ko = ks * 32;
                    uint32_t a[4], b[8][2];
                    ldsm_x4(a, aBase + ko);
                    #pragma unroll
                    for (int jj = 0; jj < 4; jj++) {
                        uint32_t r[4];
                        ldsm_x4(r, bBase + jj * 16 * ROW_PITCH + ko);
                        b[2 * jj][0]     = r[0];
                        b[2 * jj + 1][0] = r[1];
                        b[2 * jj][1]     = r[2];
                        b[2 * jj + 1][1] = r[3];
                    }
                    #pragma unroll
                    for (int j = 0; j < 8; j++)
                        mma_s8(acc[j], a, b[j]);
                }
            }

            // epilogue (tensor rows)
            const int m0 = m_base + IMMA_ROW0 + iw * 16 + lq;
            const int m1 = m0 + 8;
            const float cs0 = g_crow[m0] * wmean;
            const float cs1 = g_crow[m1] * wmean;
            const float* h0 = hh + (size_t)m0 * D_DIM;
            const float* h1 = hh + (size_t)m1 * D_DIM;
            const float* b0 = bo + (size_t)m0 * D_DIM;
            const float* b1 = bo + (size_t)m1 * D_DIM;
            float* o0 = outp + (size_t)m0 * D_DIM;
            float* o1 = outp + (size_t)m1 * D_DIM;
            #pragma unroll
            for (int j = 0; j < 8; j++) {
                const int nl = j * 8 + lr * 2;
                const int n = n_base + nl;
                const float ax = sAeff[nl], ay = sAeff[nl + 1];
                {
                    float2 hv = *(const float2*)(h0 + n);
                    float2 bv = *(const float2*)(b0 + n);
                    float2 o;
                    o.x = cs0 * (float)acc[j][0] + ax * hv.x + bv.x;
                    o.y = cs0 * (float)acc[j][1] + ay * hv.y + bv.y;
                    *(float2*)(o0 + n) = o;
                }
                {
                    float2 hv = *(const float2*)(h1 + n);
                    float2 bv = *(const float2*)(b1 + n);
                    float2 o;
                    o.x = cs1 * (float)acc[j][2] + ax * hv.x + bv.x;
                    o.y = cs1 * (float)acc[j][3] + ay * hv.y + bv.y;
                    *(float2*)(o1 + n) = o;
                }
            }
        } else {
            // ================= dp4a path: rows [0,32), 8m x 4n per thread ====
            int acc[8][4];
            #pragma unroll
            for (int i = 0; i < 8; i++)
                #pragma unroll
                for (int j = 0; j < 4; j++) acc[i][j] = 0;

            for (int kt = 0; kt < NK; ++kt) {
                cp_wait<2>();
                __syncthreads();
                if (kt + 3 < NK) prefetch(kt + 3);
                cp_commit();

                const int s = kt % STAGES;
                const char* tA = smem + s * STG_BYTES;
                const char* tB = tA + SB_OFF;

                #pragma unroll 4
                for (int kk = 0; kk < 16; kk++) {
                    int Bw[4], Aw[8];
                    #pragma unroll
                    for (int j = 0; j < 4; j++)
                        Bw[j] = *(const int*)(tB + (tx + 16 * j) * ROW_PITCH + kk * 4);
                    #pragma unroll
                    for (int i = 0; i < 8; i++)
                        Aw[i] = *(const int*)(tA + (ty + 4 * i) * ROW_PITCH + kk * 4);
                    #pragma unroll
                    for (int i = 0; i < 8; i++)
                        #pragma unroll
                        for (int j = 0; j < 4; j++)
                            acc[i][j] = __dp4a(Aw[i], Bw[j], acc[i][j]);
                }
            }

            // epilogue (dp4a rows)
            #pragma unroll
            for (int i = 0; i < 8; i++) {
                const int m = m_base + ty + 4 * i;
                const float cs = g_crow[m] * wmean;
                const float* hr = hh + (size_t)m * D_DIM + n_base;
                const float* br = bo + (size_t)m * D_DIM + n_base;
                float* orow = outp + (size_t)m * D_DIM + n_base;
                #pragma unroll
                for (int j = 0; j < 4; j++) {
                    const int nl = tx + 16 * j;
                    orow[nl] = cs * (float)acc[i][j] + sAeff[nl] * hr[nl] + br[nl];
                }
            }
        }
        __syncthreads();   // smem reuse safety across tiles
    }
}

// ============================================================================
// Host launcher — 3 launches, no padding kernels
// ============================================================================
extern "C" void kernel_launch(void* const* d_in, const int* in_sizes, int n_in,
                              void* d_out, int out_size) {
    const float* hh   = (const float*)d_in[0];
    const float* e    = (const float*)d_in[1];
    const float* bo   = (const float*)d_in[2];
    const float* araw = (const float*)d_in[3];
    const float* W    = (const float*)d_in[4];
    float* outp = (float*)d_out;

    static int sms = 148;
    static bool init_done = false;
    if (!init_done) {
        cudaDeviceGetAttribute(&sms, cudaDevAttrMultiProcessorCount, 0);
        cudaFuncSetAttribute(gemm_bitlinear_kernel,
                             cudaFuncAttributeMaxDynamicSharedMemorySize, SMEM_NEED_G);
        init_done = true;
    }

    preproc_kernel<<<M_TOTAL + D_DIM, 256>>>(e, W);
    quant_w_kernel<<<(D_DIM * (size_t)D_DIM) / 1024, 256>>>(W);
    gemm_bitlinear_kernel<<<3 * sms, 256, SMEM_NEED_G>>>(hh, bo, araw, outp);
}

// round 17
// speedup vs baseline: 1.0411x; 1.0030x over previous
#include <cuda_runtime.h>
#include <cuda_bf16.h>
#include <cstdint>
#include <cstddef>

// ============================================================================
// Problem constants
// ============================================================================
#define D_DIM   2048
#define M_TOTAL 16384

// GEMM tiling (CHAMPION config: persistent, BK64, 4-stage, occ3, hybrid 2xdp4a)
#define BM 128
#define BN 64
#define BK 64
#define NK (D_DIM / BK)          // 32 k-tiles
#define N_MP (M_TOTAL / BM)      // 128 m-panels
#define N_NP (D_DIM / BN)        // 32 n-panels
#define NTILES (N_MP * N_NP)     // 4096
#define STAGES 4
#define ROW_PITCH 80             // 64B row + 16B pad -> conflict-free LDS/LDSM
#define A_STG (BM * ROW_PITCH)   // 10240 B
#define B_STG (BN * ROW_PITCH)   // 5120 B
#define STG_BYTES (A_STG + B_STG)
#define SB_OFF A_STG
#define SCRATCH_OFF (STAGES * STG_BYTES)       // 61440: 256-float scratch
#define TICKET_OFF  (SCRATCH_OFF + 1024)       // 62464
#define SMEM_NEED_G (TICKET_OFF + 16)          // 62480 B (x3 = 187 KB < 228 KB)

// Hybrid split: warps 0..1 dp4a on rows [0,32); warps 2..7 IMMA on rows [32,128)
#define N_DP4A_WARPS 2
#define DP_ROWS      32
#define IMMA_ROW0    DP_ROWS

#define W_FLOAT4     ((D_DIM * (size_t)D_DIM) / 4)   // 1,048,576 float4 elems

// ============================================================================
// Scratch (device globals; allocation is forbidden)
// ============================================================================
__device__ int8_t g_eq[(size_t)M_TOTAL * D_DIM];   // 32 MB int8 codes of e
__device__ int8_t g_wq[(size_t)D_DIM * D_DIM];     // 4 MB ternary codes of W
__device__ float  g_crow[M_TOTAL];                 // per-row absmax/127
__device__ float  g_partial[D_DIM];                // |W| partial sums
__device__ int    g_ticket;                        // dynamic tile ticket
__device__ int    g_barrier;                       // grid-wide barrier counter

// ============================================================================
// PTX helpers (sm_80-era, valid at compute_103)
// ============================================================================
__device__ __forceinline__ uint32_t smem_u32(const void* p) {
    uint32_t a;
    asm("{ .reg .u64 t; cvta.to.shared.u64 t, %1; cvt.u32.u64 %0, t; }"
        : "=r"(a) : "l"(p));
    return a;
}

__device__ __forceinline__ void cp_async16(uint32_t saddr, const void* gaddr) {
    asm volatile("cp.async.cg.shared.global [%0], [%1], 16;"
                 :: "r"(saddr), "l"(gaddr) : "memory");
}
__device__ __forceinline__ void cp_commit() {
    asm volatile("cp.async.commit_group;" ::: "memory");
}
template <int N>
__device__ __forceinline__ void cp_wait() {
    asm volatile("cp.async.wait_group %0;" :: "n"(N) : "memory");
}

__device__ __forceinline__ void ldsm_x4(uint32_t* r, uint32_t addr) {
    asm volatile("ldmatrix.sync.aligned.m8n8.x4.shared.b16 {%0,%1,%2,%3}, [%4];"
                 : "=r"(r[0]), "=r"(r[1]), "=r"(r[2]), "=r"(r[3]) : "r"(addr));
}

__device__ __forceinline__ void mma_s8(int* c, const uint32_t* a, const uint32_t* b) {
    asm volatile(
        "mma.sync.aligned.m16n8k32.row.col.s32.s8.s8.s32 "
        "{%0,%1,%2,%3}, {%4,%5,%6,%7}, {%8,%9}, {%0,%1,%2,%3};"
        : "+r"(c[0]), "+r"(c[1]), "+r"(c[2]), "+r"(c[3])
        : "r"(a[0]), "r"(a[1]), "r"(a[2]), "r"(a[3]), "r"(b[0]), "r"(b[1]));
}

// ============================================================================
// Kernel 1 (fused): blocks [0, M_TOTAL)        -> per-row int8 quant of e
//                   blocks [M_TOTAL, +D_DIM)   -> per-row sum|W| partials
// Block 0 also resets the GEMM ticket + grid barrier (graph replays).
// ============================================================================
__global__ void __launch_bounds__(256) preproc_kernel(const float* __restrict__ e,
                                                      const float* __restrict__ W) {
    __shared__ float red[256];
    const int tid = threadIdx.x;
    if (blockIdx.x == 0 && tid == 0) { g_ticket = 0; g_barrier = 0; }

    if (blockIdx.x < M_TOTAL) {
        const int row = blockIdx.x;
        const float4* ep = (const float4*)(e + (size_t)row * D_DIM);

        float4 v0 = ep[tid];
        float4 v1 = ep[tid + 256];
        float am = fmaxf(fmaxf(fabsf(v0.x), fabsf(v0.y)), fmaxf(fabsf(v0.z), fabsf(v0.w)));
        am = fmaxf(am, fmaxf(fmaxf(fabsf(v1.x), fabsf(v1.y)), fmaxf(fabsf(v1.z), fabsf(v1.w))));
        #pragma unroll
        for (int o = 16; o > 0; o >>= 1)
            am = fmaxf(am, __shfl_xor_sync(0xFFFFFFFFu, am, o));
        if ((tid & 31) == 0) red[tid >> 5] = am;
        __syncthreads();
        if (tid == 0) {
            float a = red[0];
            #pragma unroll
            for (int i = 1; i < 8; i++) a = fmaxf(a, red[i]);
            red[0] = fmaxf(a, 1e-5f);
        }
        __syncthreads();
        const float amax = red[0];
        const float scale = 127.0f / amax;

        char4* eqp = ((char4*)g_eq) + (size_t)row * (D_DIM / 4);
        {
            char4 q;
            q.x = (char)(int)fminf(fmaxf(rintf(v0.x * scale), -128.f), 127.f);
            q.y = (char)(int)fminf(fmaxf(rintf(v0.y * scale), -128.f), 127.f);
            q.z = (char)(int)fminf(fmaxf(rintf(v0.z * scale), -128.f), 127.f);
            q.w = (char)(int)fminf(fmaxf(rintf(v0.w * scale), -128.f), 127.f);
            eqp[tid] = q;
        }
        {
            char4 q;
            q.x = (char)(int)fminf(fmaxf(rintf(v1.x * scale), -128.f), 127.f);
            q.y = (char)(int)fminf(fmaxf(rintf(v1.y * scale), -128.f), 127.f);
            q.z = (char)(int)fminf(fmaxf(rintf(v1.z * scale), -128.f), 127.f);
            q.w = (char)(int)fminf(fmaxf(rintf(v1.w * scale), -128.f), 127.f);
            eqp[tid + 256] = q;
        }
        if (tid == 0) g_crow[row] = amax / 127.0f;
    } else {
        const int wrow = blockIdx.x - M_TOTAL;
        const float4* p = (const float4*)(W + (size_t)wrow * D_DIM);
        float acc = 0.f;
        #pragma unroll
        for (int k = 0; k < 2; k++) {
            float4 v = p[tid + k * 256];
            acc += fabsf(v.x) + fabsf(v.y) + fabsf(v.z) + fabsf(v.w);
        }
        red[tid] = acc;
        __syncthreads();
        for (int st = 128; st > 0; st >>= 1) {
            if (tid < st) red[tid] += red[tid + st];
            __syncthreads();
        }
        if (tid == 0) g_partial[wrow] = red[0];
    }
}

// ============================================================================
// Kernel 2 (CHAMPION GEMM + inlined W-quant prologue, smem bug fixed):
//   Prologue: per-CTA redundant wmean reduction (256-float scratch, in-bounds),
//   grid-stride ternary quant of W, grid-wide spin barrier (all CTAs resident).
//   Mainloop: persistent hybrid IMMA + dp4a GEMM + fused epilogue.
//   warps 2..7: tensor path, rows [32,128) (warp tile 16x64)
//   warps 0..1: dp4a path, rows [0,32) — scalar LDS.32 loads (bank-tuned)
//   out[m][n] = crow[m]*wmean*acc + 0.99*tanh(A_raw[n])*h + block_out
// ============================================================================
__global__ void __launch_bounds__(256, 3) gemm_bitlinear_kernel(
    const float* __restrict__ W,
    const float* __restrict__ hh,
    const float* __restrict__ bo,
    const float* __restrict__ a_raw,
    float* __restrict__ outp)
{
    extern __shared__ char smem[];
    const uint32_t sbase = smem_u32(smem);
    float* sScratch = (float*)(smem + SCRATCH_OFF);   // 256 floats
    float* sAeff = sScratch;                          // first 64 reused per tile
    int* sTicket = (int*)(smem + TICKET_OFF);

    const int tid = threadIdx.x;
    const int wid = tid >> 5;
    const int lane = tid & 31;

    // ---- prologue: wmean (redundant, deterministic — same sum as quant_w) --
    {
        float acc = 0.f;
        #pragma unroll
        for (int k = 0; k < 8; k++) acc += g_partial[tid + k * 256];
        sScratch[tid] = acc;
        __syncthreads();
        for (int st = 128; st > 0; st >>= 1) {
            if (tid < st) sScratch[tid] += sScratch[tid + st];
            __syncthreads();
        }
    }
    const float wmean = fmaxf(sScratch[0] / 4194304.0f, 1e-5f);
    __syncthreads();

    // ---- prologue: grid-stride ternary quant of W ----
    {
        const float inv = 1.0f / wmean;
        const size_t stride = (size_t)gridDim.x * 256;
        for (size_t idx = (size_t)blockIdx.x * 256 + tid; idx < W_FLOAT4; idx += stride) {
            float4 v = ((const float4*)W)[idx];
            char4 q;
            q.x = (char)(int)fminf(fmaxf(rintf(v.x * inv), -1.f), 1.f);
            q.y = (char)(int)fminf(fmaxf(rintf(v.y * inv), -1.f), 1.f);
            q.z = (char)(int)fminf(fmaxf(rintf(v.z * inv), -1.f), 1.f);
            q.w = (char)(int)fminf(fmaxf(rintf(v.w * inv), -1.f), 1.f);
            ((char4*)g_wq)[idx] = q;
        }
    }

    // ---- grid-wide barrier (all CTAs resident: grid == 3 * SMs, occ 3) ----
    __threadfence();
    __syncthreads();
    if (tid == 0) {
        atomicAdd(&g_barrier, 1);
        while (atomicAdd(&g_barrier, 0) < (int)gridDim.x) { }
    }
    __syncthreads();

    // ---- champion GEMM (byte-identical to R13/R15 mainloop) ----
    // prefetch thread coords (all threads)
    const int a0row = tid >> 2, a0col = (tid & 3) * 16;
    const int a1row = (tid + 256) >> 2;
    const int brow  = tid >> 2;

    // IMMA-path constants (warps 2..7)
    const int lq = lane >> 2;
    const int lr = lane & 3;
    const uint32_t lm_row  = (uint32_t)(lane & 15);
    const uint32_t lm_half = (uint32_t)((lane >> 4) * 16);
    const int iw = wid - N_DP4A_WARPS;            // 0..5 for imma warps
    const uint32_t aOffW = (uint32_t)((IMMA_ROW0 + iw * 16) + (int)lm_row) * ROW_PITCH + lm_half;
    const uint32_t bOffW = lm_row * ROW_PITCH + lm_half;

    // dp4a-path constants (warps 0..1): thread grid 4(ty) x 16(tx)
    const int ty = (wid << 1) | (lane >> 4);      // 0..3
    const int tx = lane & 15;

    for (;;) {
        if (tid == 0) *sTicket = atomicAdd(&g_ticket, 1);
        __syncthreads();
        const int t = *sTicket;
        if (t >= NTILES) break;
        const int m_base = (t >> 5) * BM;
        const int n_base = (t & 31) * BN;

        if (tid < BN) sAeff[tid] = 0.99f * tanhf(a_raw[n_base + tid]);

        const int8_t* Ag = g_eq + (size_t)m_base * D_DIM;
        const int8_t* Bg = g_wq + (size_t)n_base * D_DIM;

        auto prefetch = [&](int kt) {
            const int s = kt % STAGES;
            const int k0 = kt * BK;
            const uint32_t sA = sbase + s * STG_BYTES;
            const uint32_t sB = sA + SB_OFF;
            cp_async16(sA + a0row * ROW_PITCH + a0col, Ag + (size_t)a0row * D_DIM + k0 + a0col);
            cp_async16(sA + a1row * ROW_PITCH + a0col, Ag + (size_t)a1row * D_DIM + k0 + a0col);
            cp_async16(sB + brow * ROW_PITCH + a0col,  Bg + (size_t)brow * D_DIM + k0 + a0col);
        };

        prefetch(0); cp_commit();
        prefetch(1); cp_commit();
        prefetch(2); cp_commit();

        if (wid >= N_DP4A_WARPS) {
            // ================= tensor path: 96 rows, warp tile 16x64 =========
            int acc[8][4];
            #pragma unroll
            for (int j = 0; j < 8; j++)
                #pragma unroll
                for (int r = 0; r < 4; r++) acc[j][r] = 0;

            for (int kt = 0; kt < NK; ++kt) {
                cp_wait<2>();
                __syncthreads();
                if (kt + 3 < NK) prefetch(kt + 3);
                cp_commit();

                const int s = kt % STAGES;
                const uint32_t aBase = sbase + s * STG_BYTES + aOffW;
                const uint32_t bBase = sbase + s * STG_BYTES + SB_OFF + bOffW;

                #pragma unroll
                for (int ks = 0; ks < 2; ks++) {
                    const int ko = ks * 32;
                    uint32_t a[4], b[8][2];
                    ldsm_x4(a, aBase + ko);
                    #pragma unroll
                    for (int jj = 0; jj < 4; jj++) {
                        uint32_t r[4];
                        ldsm_x4(r, bBase + jj * 16 * ROW_PITCH + ko);
                        b[2 * jj][0]     = r[0];
                        b[2 * jj + 1][0] = r[1];
                        b[2 * jj][1]     = r[2];
                        b[2 * jj + 1][1] = r[3];
                    }
                    #pragma unroll
                    for (int j = 0; j < 8; j++)
                        mma_s8(acc[j], a, b[j]);
                }
            }

            // epilogue (tensor rows)
            const int m0 = m_base + IMMA_ROW0 + iw * 16 + lq;
            const int m1 = m0 + 8;
            const float cs0 = g_crow[m0] * wmean;
            const float cs1 = g_crow[m1] * wmean;
            const float* h0 = hh + (size_t)m0 * D_DIM;
            const float* h1 = hh + (size_t)m1 * D_DIM;
            const float* b0 = bo + (size_t)m0 * D_DIM;
            const float* b1 = bo + (size_t)m1 * D_DIM;
            float* o0 = outp + (size_t)m0 * D_DIM;
            float* o1 = outp + (size_t)m1 * D_DIM;
            #pragma unroll
            for (int j = 0; j < 8; j++) {
                const int nl = j * 8 + lr * 2;
                const int n = n_base + nl;
                const float ax = sAeff[nl], ay = sAeff[nl + 1];
                {
                    float2 hv = *(const float2*)(h0 + n);
                    float2 bv = *(const float2*)(b0 + n);
                    float2 o;
                    o.x = cs0 * (float)acc[j][0] + ax * hv.x + bv.x;
                    o.y = cs0 * (float)acc[j][1] + ay * hv.y + bv.y;
                    *(float2*)(o0 + n) = o;
                }
                {
                    float2 hv = *(const float2*)(h1 + n);
                    float2 bv = *(const float2*)(b1 + n);
                    float2 o;
                    o.x = cs1 * (float)acc[j][2] + ax * hv.x + bv.x;
                    o.y = cs1 * (float)acc[j][3] + ay * hv.y + bv.y;
                    *(float2*)(o1 + n) = o;
                }
            }
        } else {
            // ================= dp4a path: rows [0,32), 8m x 4n per thread ====
            int acc[8][4];
            #pragma unroll
            for (int i = 0; i < 8; i++)
                #pragma unroll
                for (int j = 0; j < 4; j++) acc[i][j] = 0;

            for (int kt = 0; kt < NK; ++kt) {
                cp_wait<2>();
                __syncthreads();
                if (kt + 3 < NK) prefetch(kt + 3);
                cp_commit();

                const int s = kt % STAGES;
                const char* tA = smem + s * STG_BYTES;
                const char* tB = tA + SB_OFF;

                #pragma unroll 4
                for (int kk = 0; kk < 16; kk++) {
                    int Bw[4], Aw[8];
                    #pragma unroll
                    for (int j = 0; j < 4; j++)
                        Bw[j] = *(const int*)(tB + (tx + 16 * j) * ROW_PITCH + kk * 4);
                    #pragma unroll
                    for (int i = 0; i < 8; i++)
                        Aw[i] = *(const int*)(tA + (ty + 4 * i) * ROW_PITCH + kk * 4);
                    #pragma unroll
                    for (int i = 0; i < 8; i++)
                        #pragma unroll
                        for (int j = 0; j < 4; j++)
                            acc[i][j] = __dp4a(Aw[i], Bw[j], acc[i][j]);
                }
            }

            // epilogue (dp4a rows)
            #pragma unroll
            for (int i = 0; i < 8; i++) {
                const int m = m_base + ty + 4 * i;
                const float cs = g_crow[m] * wmean;
                const float* hr = hh + (size_t)m * D_DIM + n_base;
                const float* br = bo + (size_t)m * D_DIM + n_base;
                float* orow = outp + (size_t)m * D_DIM + n_base;
                #pragma unroll
                for (int j = 0; j < 4; j++) {
                    const int nl = tx + 16 * j;
                    orow[nl] = cs * (float)acc[i][j] + sAeff[nl] * hr[nl] + br[nl];
                }
            }
        }
        __syncthreads();   // smem reuse safety across tiles
    }
}

// ============================================================================
// Host launcher — 2 launches (quant_w inlined into the persistent GEMM)
// ============================================================================
extern "C" void kernel_launch(void* const* d_in, const int* in_sizes, int n_in,
                              void* d_out, int out_size) {
    const float* hh   = (const float*)d_in[0];
    const float* e    = (const float*)d_in[1];
    const float* bo   = (const float*)d_in[2];
    const float* araw = (const float*)d_in[3];
    const float* W    = (const float*)d_in[4];
    float* outp = (float*)d_out;

    static int sms = 148;
    static bool init_done = false;
    if (!init_done) {
        cudaDeviceGetAttribute(&sms, cudaDevAttrMultiProcessorCount, 0);
        cudaFuncSetAttribute(gemm_bitlinear_kernel,
                             cudaFuncAttributeMaxDynamicSharedMemorySize, SMEM_NEED_G);
        init_done = true;
    }

    preproc_kernel<<<M_TOTAL + D_DIM, 256>>>(e, W);
    gemm_bitlinear_kernel<<<3 * sms, 256, SMEM_NEED_G>>>(W, hh, bo, araw, outp);
}